// round 8
// baseline (speedup 1.0000x reference)
#include <cuda_runtime.h>
#include <cuda_bf16.h>
#include <math.h>
#include <stdint.h>

// ---------------- problem constants ----------------
#define BB    4096
#define TT    32
#define VOCAB 10000
#define EE    300
#define HH    300
#define KSEG  320      // padded K per segment
#define KP2   640      // hi|lo storage columns
#define NP    1280     // 4H padded
#define MV    10112    // vocab padded to 128
#define NC    15       // K chunks of 64 (3 segments x 5)
#define MT    128
#define NT    128
#define NSTAGE 3
#define ROWB  144      // smem row stride bytes (64 cols * 2B + 16 pad)

// smem (dynamic) layout, bytes
#define SM_CAP   0          // 128 int
#define SM_LEN   512        // 128 int
#define SM_BIAS  1024       // 128 float
#define SM_STAGE 2048       // 3 stages x (A 18432 + B 18432)
#define STAGE_BYTES (2 * 128 * ROWB)                    // 36864
#define SMEM_TOTAL (SM_STAGE + NSTAGE * STAGE_BYTES)    // 112640

// ---------------- device scratch ----------------
__device__ __nv_bfloat16 g_emb2[(size_t)MV * KP2];
__device__ __nv_bfloat16 g_wih2[(size_t)NP * KP2];
__device__ __nv_bfloat16 g_whh2[(size_t)NP * KP2];
__device__ float         g_bias[NP];
__device__ float         g_xproj[(size_t)MV * NP];
__device__ __nv_bfloat16 g_h2[2][(size_t)BB * KP2];
__device__ float         g_c[(size_t)BB * KSEG];
__device__ float         g_hlast[BB * HH];
__device__ float         g_wn[2 * HH];

// ---------------- PTX helpers (plain sm_80+ instructions only) ----------------
__device__ __forceinline__ uint32_t smem_u32(const void* p) {
    uint32_t a;
    asm("{ .reg .u64 t; cvta.to.shared.u64 t, %1; cvt.u32.u64 %0, t; }" : "=r"(a) : "l"(p));
    return a;
}
__device__ __forceinline__ void cp_async16(uint32_t s, const void* g) {
    asm volatile("cp.async.cg.shared.global [%0], [%1], 16;" :: "r"(s), "l"(g) : "memory");
}
__device__ __forceinline__ void cp_commit() {
    asm volatile("cp.async.commit_group;" ::: "memory");
}
__device__ __forceinline__ void cp_wait1() {
    asm volatile("cp.async.wait_group 1;" ::: "memory");
}
__device__ __forceinline__ void l2_prefetch(const void* g) {
    asm volatile("prefetch.global.L2 [%0];" :: "l"(g));
}
__device__ __forceinline__ void ldsm_x4(uint32_t* r, uint32_t addr) {
    asm volatile("ldmatrix.sync.aligned.m8n8.x4.shared.b16 {%0,%1,%2,%3}, [%4];"
                 : "=r"(r[0]), "=r"(r[1]), "=r"(r[2]), "=r"(r[3]) : "r"(addr));
}
__device__ __forceinline__ void ldsm_x2(uint32_t* r, uint32_t addr) {
    asm volatile("ldmatrix.sync.aligned.m8n8.x2.shared.b16 {%0,%1}, [%2];"
                 : "=r"(r[0]), "=r"(r[1]) : "r"(addr));
}
__device__ __forceinline__ void mma16816(float* c, const uint32_t* a, const uint32_t* b) {
    asm volatile(
        "mma.sync.aligned.m16n8k16.row.col.f32.bf16.bf16.f32 "
        "{%0,%1,%2,%3}, {%4,%5,%6,%7}, {%8,%9}, {%0,%1,%2,%3};"
        : "+f"(c[0]), "+f"(c[1]), "+f"(c[2]), "+f"(c[3])
        : "r"(a[0]), "r"(a[1]), "r"(a[2]), "r"(a[3]), "r"(b[0]), "r"(b[1]));
}
__device__ __forceinline__ float fsig(float x)  { return 1.f / (1.f + __expf(-x)); }
__device__ __forceinline__ float ftanh(float x) { return 1.f - 2.f / (1.f + __expf(2.f * x)); }

// ---------------- prep: fp32 -> bf16 hi|lo split, gate interleave, zero state ----------------
__global__ void k_prep(const float* __restrict__ embed_w,
                       const float* __restrict__ W_ih,
                       const float* __restrict__ W_hh,
                       const float* __restrict__ b_ih,
                       const float* __restrict__ b_hh)
{
    const int stride = gridDim.x * blockDim.x;
    const int i0 = blockIdx.x * blockDim.x + threadIdx.x;

    for (size_t idx = i0; idx < (size_t)MV * KP2; idx += stride) {
        int r = idx / KP2, k2 = idx - (size_t)r * KP2;
        int k = (k2 >= KSEG) ? k2 - KSEG : k2;
        float v = (r < VOCAB && k < EE) ? embed_w[r * EE + k] : 0.f;
        __nv_bfloat16 hi = __float2bfloat16_rn(v);
        g_emb2[idx] = (k2 >= KSEG) ? __float2bfloat16_rn(v - __bfloat162float(hi)) : hi;
    }
    for (size_t idx = i0; idx < (size_t)NP * KP2; idx += stride) {
        int n = idx / KP2, k2 = idx - (size_t)n * KP2;
        int k = (k2 >= KSEG) ? k2 - KSEG : k2;
        int gs = n & 3, u = n >> 2;
        float vi = 0.f, vh = 0.f;
        if (u < HH && k < EE) {
            int s = (gs * HH + u) * EE + k;
            vi = W_ih[s];
            vh = W_hh[s];
        }
        __nv_bfloat16 hi_i = __float2bfloat16_rn(vi);
        __nv_bfloat16 hi_h = __float2bfloat16_rn(vh);
        if (k2 >= KSEG) {
            g_wih2[idx] = __float2bfloat16_rn(vi - __bfloat162float(hi_i));
            g_whh2[idx] = __float2bfloat16_rn(vh - __bfloat162float(hi_h));
        } else {
            g_wih2[idx] = hi_i;
            g_whh2[idx] = hi_h;
        }
    }
    for (int n = i0; n < NP; n += stride) {
        int gs = n & 3, u = n >> 2;
        g_bias[n] = (u < HH) ? (b_ih[gs * HH + u] + b_hh[gs * HH + u]) : 0.f;
    }
    for (size_t idx = i0; idx < (size_t)BB * KP2; idx += stride) {
        g_h2[0][idx] = __float2bfloat16_rn(0.f);
        g_h2[1][idx] = __float2bfloat16_rn(0.f);
    }
    for (size_t idx = i0; idx < (size_t)BB * KSEG; idx += stride)
        g_c[idx] = 0.f;
}

__global__ void k_prep_cls(const float* __restrict__ cls_v,
                           const float* __restrict__ cls_g)
{
    int w = threadIdx.x >> 5;
    int lane = threadIdx.x & 31;
    if (w >= 2) return;
    float s = 0.f;
    for (int k = lane; k < HH; k += 32) {
        float v = cls_v[w * HH + k];
        s += v * v;
    }
    #pragma unroll
    for (int o = 16; o; o >>= 1) s += __shfl_xor_sync(0xffffffff, s, o);
    float scale = cls_g[w] / sqrtf(s);
    for (int k = lane; k < HH; k += 32)
        g_wn[w * HH + k] = cls_v[w * HH + k] * scale;
}

// ---------------- HMMA GEMM: C[128,128] = A[128,960] x B[128,960]^T ----------------
// Extended K: A chunks [hi|lo|hi], B chunks [hi|hi|lo]
// MODE 0: A=g_emb2, B=g_wih2 -> store g_xproj
// MODE 1: A=g_h2[parity], B=g_whh2 -> fused LSTM epilogue
template <int MODE>
__global__ void __launch_bounds__(256, 2) k_tgemm(int t, int parity,
                                                  const int* __restrict__ cap,
                                                  const int* __restrict__ cap_len)
{
    extern __shared__ char smem[];
    const uint32_t sb = smem_u32(smem);
    const int tid = threadIdx.x;
    const int wid = tid >> 5;
    const int lane = tid & 31;
    const int wm = wid >> 2;         // 0..1 : 64-row slice
    const int wn = wid & 3;          // 0..3 : 32-col slice
    const int m0 = blockIdx.y * MT;
    const int n0 = blockIdx.x * NT;

    const __nv_bfloat16* Ag = (MODE == 0) ? g_emb2 : g_h2[parity];
    const __nv_bfloat16* Bg = (MODE == 0) ? g_wih2 : g_whh2;

    if (MODE == 1) {
        if (tid < 128) {
            const int tok = cap[(m0 + tid) * TT + t];
            ((int*)(smem + SM_CAP))[tid] = tok;
            ((int*)(smem + SM_LEN))[tid] = cap_len[m0 + tid];
            // warm L2 for the epilogue gather (this CTA's 128-col slice of row tok)
            const char* pr = (const char*)(g_xproj + (size_t)tok * NP + n0);
            l2_prefetch(pr);
            l2_prefetch(pr + 128);
            l2_prefetch(pr + 256);
            l2_prefetch(pr + 384);
        } else {
            ((float*)(smem + SM_BIAS))[tid - 128] = g_bias[n0 + tid - 128];
        }
    }

    // loader geometry: per chunk A = 128x64 bf16 (128 rows x 8 x 16B units), B same.
    // 256 threads x 4 contiguous units each.
    const int a_row = tid >> 1;           // unit id = tid*4+i -> row = (tid*4)>>3 = tid>>1
    const int a_cu  = (tid & 1) * 4;      // first of 4 consecutive 16B units

    uint32_t stA[NSTAGE], stB[NSTAGE];
    #pragma unroll
    for (int s = 0; s < NSTAGE; s++) {
        stA[s] = sb + SM_STAGE + s * STAGE_BYTES;
        stB[s] = stA[s] + 128 * ROWB;
    }

    auto issue_chunk = [&](int c) {
        if (c < NC) {
            const int stage = c % 3;
            const int seg = c / 5, within = (c - seg * 5) * 64;
            const int aoff = ((seg == 1) ? KSEG : 0) + within;
            const int boff = ((seg == 2) ? KSEG : 0) + within;
            const __nv_bfloat16* ap = Ag + (size_t)(m0 + a_row) * KP2 + aoff + a_cu * 8;
            const __nv_bfloat16* bp = Bg + (size_t)(n0 + a_row) * KP2 + boff + a_cu * 8;
            const uint32_t sa  = stA[stage] + a_row * ROWB + a_cu * 16;
            const uint32_t sbm = stB[stage] + a_row * ROWB + a_cu * 16;
            #pragma unroll
            for (int i = 0; i < 4; i++) {
                cp_async16(sa + i * 16, ap + i * 8);
                cp_async16(sbm + i * 16, bp + i * 8);
            }
        }
        cp_commit();
    };

    float acc[4][4][4];
    #pragma unroll
    for (int i = 0; i < 4; i++)
        #pragma unroll
        for (int j = 0; j < 4; j++)
            #pragma unroll
            for (int e = 0; e < 4; e++) acc[i][j][e] = 0.f;

    const uint32_t a_lrow = (uint32_t)(wm * 64 + (lane & 15)) * ROWB;
    const uint32_t a_kofs = (uint32_t)((lane >> 4) * 16);
    const uint32_t b_lrow = (uint32_t)(wn * 32 + (lane & 7)) * ROWB;
    const uint32_t b_kofs = (uint32_t)(((lane >> 3) & 1) * 16);

    issue_chunk(0);
    issue_chunk(1);

    for (int c = 0; c < NC; c++) {
        cp_wait1();
        __syncthreads();
        issue_chunk(c + 2);                 // into stage freed last iteration
        const int stage = c % 3;
        const uint32_t sA = stA[stage], sB = stB[stage];
        #pragma unroll
        for (int k16 = 0; k16 < 4; k16++) {
            uint32_t a[4][4], b[4][2];
            #pragma unroll
            for (int i = 0; i < 4; i++)
                ldsm_x4(a[i], sA + a_lrow + i * 16 * ROWB + k16 * 32 + a_kofs);
            #pragma unroll
            for (int j = 0; j < 4; j++)
                ldsm_x2(b[j], sB + b_lrow + j * 8 * ROWB + k16 * 32 + b_kofs);
            #pragma unroll
            for (int i = 0; i < 4; i++)
                #pragma unroll
                for (int j = 0; j < 4; j++)
                    mma16816(acc[i][j], a[i], b[j]);
        }
    }

    // ---------------- epilogue ----------------
    const int lr_base = wm * 64 + (lane >> 2);
    const int nl_base = wn * 32 + 2 * (lane & 3);
    const bool odd = lane & 1;

    if (MODE == 0) {
        #pragma unroll
        for (int i = 0; i < 4; i++) {
            const int r0 = m0 + lr_base + i * 16;
            #pragma unroll
            for (int j = 0; j < 4; j++) {
                const int ng = n0 + nl_base + j * 8;
                *(float2*)(g_xproj + (size_t)r0 * NP + ng) = make_float2(acc[i][j][0], acc[i][j][1]);
                *(float2*)(g_xproj + (size_t)(r0 + 8) * NP + ng) = make_float2(acc[i][j][2], acc[i][j][3]);
            }
        }
    } else {
        const int* s_cap = (const int*)(smem + SM_CAP);
        const int* s_len = (const int*)(smem + SM_LEN);
        const float* s_bias = (const float*)(smem + SM_BIAS);
        __nv_bfloat16* hout = g_h2[parity ^ 1];

        #pragma unroll
        for (int i = 0; i < 4; i++) {
            const int lr0 = lr_base + i * 16;
            const int r0 = m0 + lr0, r1 = r0 + 8;
            const int tok0 = s_cap[lr0], tok1 = s_cap[lr0 + 8];
            const int  rme    = odd ? r1 : r0;
            const bool lastme = odd ? (t == s_len[lr0 + 8] - 1) : (t == s_len[lr0] - 1);
            #pragma unroll
            for (int j = 0; j < 4; j++) {
                const int nl = nl_base + j * 8;
                const int ng = n0 + nl;
                const float2 x0 = *(const float2*)(g_xproj + (size_t)tok0 * NP + ng);
                const float2 x1 = *(const float2*)(g_xproj + (size_t)tok1 * NP + ng);
                const float2 bi = *(const float2*)(s_bias + nl);
                float v0 = acc[i][j][0] + x0.x + bi.x;
                float v1 = acc[i][j][1] + x0.y + bi.y;
                float v2 = acc[i][j][2] + x1.x + bi.x;
                float v3 = acc[i][j][3] + x1.y + bi.y;
                // partner exchange: even lane owns (i,f), odd owns (g,o)
                float o0 = __shfl_xor_sync(0xffffffff, v0, 1);
                float o1 = __shfl_xor_sync(0xffffffff, v1, 1);
                float o2 = __shfl_xor_sync(0xffffffff, v2, 1);
                float o3 = __shfl_xor_sync(0xffffffff, v3, 1);
                float gi, gf, gg, go;
                if (!odd) { gi = v0; gf = v1; gg = o0; go = o1; }   // row0
                else      { gi = o2; gf = o3; gg = v2; go = v3; }   // row1
                const int u = (ng - (odd ? 2 : 0)) >> 2;            // hidden unit
                float I = fsig(gi), F = fsig(gf), G = ftanh(gg), O = fsig(go);
                float cn = F * g_c[(size_t)rme * KSEG + u] + I * G;
                float hn = O * ftanh(cn);
                g_c[(size_t)rme * KSEG + u] = cn;
                __nv_bfloat16 hb = __float2bfloat16_rn(hn);
                hout[(size_t)rme * KP2 + u] = hb;
                hout[(size_t)rme * KP2 + KSEG + u] =
                    __float2bfloat16_rn(hn - __bfloat162float(hb));
                if (lastme && u < HH) g_hlast[rme * HH + u] = hn;
            }
        }
    }
}

// ---------------- classifier ----------------
__global__ void k_cls(const float* __restrict__ cls_b, float* __restrict__ out)
{
    int warp = (blockIdx.x * blockDim.x + threadIdx.x) >> 5;
    int lane = threadIdx.x & 31;
    if (warp >= BB) return;
    float s0 = 0.f, s1 = 0.f;
    for (int k = lane; k < HH; k += 32) {
        float hv = g_hlast[warp * HH + k];
        s0 += hv * g_wn[k];
        s1 += hv * g_wn[HH + k];
    }
    #pragma unroll
    for (int o = 16; o; o >>= 1) {
        s0 += __shfl_xor_sync(0xffffffff, s0, o);
        s1 += __shfl_xor_sync(0xffffffff, s1, o);
    }
    if (lane == 0) {
        out[warp * 2 + 0] = s0 + cls_b[0];
        out[warp * 2 + 1] = s1 + cls_b[1];
    }
}

extern "C" void kernel_launch(void* const* d_in, const int* in_sizes, int n_in,
                              void* d_out, int out_size)
{
    const int*   cap     = (const int*)d_in[0];
    const int*   cap_len = (const int*)d_in[1];
    const float* embed_w = (const float*)d_in[2];
    const float* W_ih    = (const float*)d_in[3];
    const float* W_hh    = (const float*)d_in[4];
    const float* b_ih    = (const float*)d_in[5];
    const float* b_hh    = (const float*)d_in[6];
    const float* cls_v   = (const float*)d_in[7];
    const float* cls_g   = (const float*)d_in[8];
    const float* cls_b   = (const float*)d_in[9];
    float* out = (float*)d_out;

    cudaFuncSetAttribute(k_tgemm<0>, cudaFuncAttributeMaxDynamicSharedMemorySize, SMEM_TOTAL);
    cudaFuncSetAttribute(k_tgemm<1>, cudaFuncAttributeMaxDynamicSharedMemorySize, SMEM_TOTAL);

    k_prep<<<2048, 256>>>(embed_w, W_ih, W_hh, b_ih, b_hh);
    k_prep_cls<<<1, 64>>>(cls_v, cls_g);

    {   // x_proj = emb @ W_ih^T
        dim3 grid(NP / NT, MV / MT);   // (10, 79)
        k_tgemm<0><<<grid, 256, SMEM_TOTAL>>>(0, 0, nullptr, nullptr);
    }
    {   // 32 fused recurrent steps
        dim3 grid(NP / NT, BB / MT);   // (10, 32) = 320 CTAs, 2 per SM
        for (int t = 0; t < TT; t++)
            k_tgemm<1><<<grid, 256, SMEM_TOTAL>>>(t, t & 1, cap, cap_len);
    }
    k_cls<<<512, 256>>>(cls_b, out);
}